// round 17
// baseline (speedup 1.0000x reference)
#include <cuda_runtime.h>
#include <cuda_bf16.h>

// x: (1, 256, 512, 512) fp32 -> out: (1, 64, 512, 512), mean over groups of 4 channels.
// HW4 = 512*512/4 = 65536 float4 per channel plane.
// out[c][p] = 0.25 * (x[4c][p] + x[4c+1][p] + x[4c+2][p] + x[4c+3][p])
//
// Converged memory-roofline kernel (45.6-45.8us kernel time, DRAM ~85%,
// 6.7 TB/s; traffic minimal at 320MB):
//  - one output float4 per thread, lanes fully coalesced (128B/warp request)
//  - 4 independent front-batched LDG.128 (MLP=4), input planes 1MB apart
//  - __ldcs/__stcs evict-first for the single-touch stream (measured -1.7us
//    kernel vs default policy)
//  - 256-thread blocks / 16384-block launch: finer tail granularity
// Rejected by measurement: MLP=8 split-halves, persistent 592-CTA grid,
// 2-consecutive-float4/thread (sector-split), plain cache policy.

static constexpr int HW4 = (512 * 512) / 4;   // 65536
static constexpr int C_OUT = 64;
static constexpr int THREADS = 256;

__global__ __launch_bounds__(THREADS)
void spectral_blurrin_kernel(const float4* __restrict__ x,
                             float4* __restrict__ out) {
    const int p = blockIdx.x * THREADS + threadIdx.x;   // position within plane (float4 units)
    const int c = blockIdx.y;                           // output channel

    const float4* in0 = x + (long long)c * 4 * HW4 + p;

    // 4 independent 128-bit streaming loads, 1 MB apart -> front-batched, MLP=4
    const float4 a = __ldcs(in0);
    const float4 b = __ldcs(in0 + HW4);
    const float4 d = __ldcs(in0 + 2 * HW4);
    const float4 e = __ldcs(in0 + 3 * HW4);

    float4 r;
    r.x = (a.x + b.x + d.x + e.x) * 0.25f;
    r.y = (a.y + b.y + d.y + e.y) * 0.25f;
    r.z = (a.z + b.z + d.z + e.z) * 0.25f;
    r.w = (a.w + b.w + d.w + e.w) * 0.25f;

    __stcs(out + (long long)c * HW4 + p, r);
}

extern "C" void kernel_launch(void* const* d_in, const int* in_sizes, int n_in,
                              void* d_out, int out_size) {
    const float4* x = (const float4*)d_in[0];
    float4* out = (float4*)d_out;

    dim3 grid(HW4 / THREADS, C_OUT);   // (256, 64) = 16384 blocks
    spectral_blurrin_kernel<<<grid, THREADS>>>(x, out);
}